// round 1
// baseline (speedup 1.0000x reference)
#include <cuda_runtime.h>
#include <math.h>
#include <stdint.h>

// Problem constants
#define E_DIM   256
#define NA      900
#define BS      2
#define NCAM    6
#define NLVL    4
#define NPTS    13
#define NG      8
#define NANCH   (BS*NA)          // 1800
#define WO      416              // G*NL*NPTS = 8*4*13
#define NSAMP   (NCAM*NLVL*NPTS) // 312
#define SOFTN   312              // softmax length per group

// Feature-map level shapes
// level: H, W
// 0: 64,176  1: 32,88  2: 16,44  3: 8,22

// -------- device scratch (no runtime allocation allowed) --------
__device__ float g_fmt0[34603008];   // [12][64*176][256]
__device__ float g_fmt1[8650752];    // [12][32*88][256]
__device__ float g_fmt2[2162688];    // [12][16*44][256]
__device__ float g_fmt3[540672];     // [12][8*22][256]
__device__ float g_featW[NANCH*WO];  // (feat+anchor_embed) @ wfc_w   (no bias)
__device__ float g_ceWb[12*WO];      // ce @ wfc_w + wfc_b
__device__ float g_fused[NANCH*E_DIM];

__constant__ float c_fix[7][3] = {
  {0.f,0.f,0.f},{0.45f,0.f,0.f},{-0.45f,0.f,0.f},{0.f,0.45f,0.f},
  {0.f,-0.45f,0.f},{0.f,0.f,0.45f},{0.f,0.f,-0.45f}};

// ---------------- transpose [b,c,E,H,W] -> [b,c,H,W,E] ----------------
__global__ void transpose_kernel(const float* __restrict__ src, int level){
  float* dst; int HW;
  if(level==0){dst=g_fmt0; HW=11264;} else if(level==1){dst=g_fmt1; HW=2816;}
  else if(level==2){dst=g_fmt2; HW=704;} else {dst=g_fmt3; HW=176;}
  __shared__ float tile[32][33];
  int img = blockIdx.z;
  const float* s = src + (size_t)img * E_DIM * HW;
  float* d       = dst + (size_t)img * HW * E_DIM;
  int hw0 = blockIdx.x*32, e0 = blockIdx.y*32;
  int tx = threadIdx.x, ty = threadIdx.y;
  #pragma unroll
  for(int i=ty;i<32;i+=8){
    int hw = hw0+tx;
    tile[i][tx] = (hw<HW) ? s[(size_t)(e0+i)*HW + hw] : 0.f;
  }
  __syncthreads();
  #pragma unroll
  for(int i=ty;i<32;i+=8){
    int hw = hw0+i;
    if(hw<HW) d[(size_t)hw*E_DIM + (e0+tx)] = tile[tx][i];
  }
}

// ---------------- camera embed: 12 rows MLP + LN, then @wfc_w ----------------
__device__ __forceinline__ float blockSum256(float v, float* red){
  int tid = threadIdx.x;
  red[tid] = v; __syncthreads();
  #pragma unroll
  for(int s=128;s>0;s>>=1){
    if(tid<s) red[tid]+=red[tid+s];
    __syncthreads();
  }
  float r = red[0]; __syncthreads();
  return r;
}

__global__ void cam_embed_kernel(const float* __restrict__ pm,
    const float* __restrict__ ce1w, const float* __restrict__ ce1b,
    const float* __restrict__ ln1g, const float* __restrict__ ln1b,
    const float* __restrict__ ce2w, const float* __restrict__ ce2b,
    const float* __restrict__ ln2g, const float* __restrict__ ln2b,
    const float* __restrict__ wfcw, const float* __restrict__ wfcb){
  int img = blockIdx.x;          // b*6+c, 12 blocks
  int tid = threadIdx.x;         // 256
  __shared__ float cam[12];
  __shared__ float h[E_DIM];
  __shared__ float red[E_DIM];
  if(tid<12) cam[tid] = pm[img*16 + tid];   // first 3 rows of 4x4, row-major
  __syncthreads();
  // layer 1
  float v = ce1b[tid];
  #pragma unroll
  for(int i=0;i<12;i++) v += cam[i]*ce1w[i*E_DIM+tid];
  v = fmaxf(v,0.f);
  float m = blockSum256(v, red) * (1.f/E_DIM);
  float dvar = v - m;
  float var = blockSum256(dvar*dvar, red) * (1.f/E_DIM);
  v = dvar * rsqrtf(var + 1e-5f) * ln1g[tid] + ln1b[tid];
  h[tid] = v; __syncthreads();
  // layer 2
  float v2 = ce2b[tid];
  for(int i=0;i<E_DIM;i++) v2 += h[i]*ce2w[i*E_DIM+tid];
  v2 = fmaxf(v2,0.f);
  __syncthreads();           // h still in use above? loop done; safe before overwrite
  float m2 = blockSum256(v2, red) * (1.f/E_DIM);
  float d2 = v2 - m2;
  float var2 = blockSum256(d2*d2, red) * (1.f/E_DIM);
  v2 = d2 * rsqrtf(var2 + 1e-5f) * ln2g[tid] + ln2b[tid];
  h[tid] = v2; __syncthreads();
  // ceWb = ce @ wfc_w + wfc_b
  for(int o=tid;o<WO;o+=256){
    float a = wfcb[o];
    for(int e=0;e<E_DIM;e++) a += h[e]*wfcw[e*WO+o];
    g_ceWb[img*WO+o] = a;
  }
}

// ---------------- featW = (instance_feature + anchor_embed) @ wfc_w ----------------
__global__ __launch_bounds__(256) void featw_kernel(const float* __restrict__ iff,
    const float* __restrict__ ae, const float* __restrict__ wfcw){
  __shared__ float fs[32][E_DIM];
  int a0 = blockIdx.x*32;
  int tid = threadIdx.x;
  #pragma unroll 4
  for(int m=0;m<32;m++){
    int a = a0+m;
    fs[m][tid] = (a<NANCH) ? (iff[(size_t)a*E_DIM+tid] + ae[(size_t)a*E_DIM+tid]) : 0.f;
  }
  __syncthreads();
  for(int o=tid;o<WO;o+=256){
    float acc[32];
    #pragma unroll
    for(int m=0;m<32;m++) acc[m]=0.f;
    for(int e=0;e<E_DIM;e++){
      float wv = wfcw[e*WO+o];
      #pragma unroll
      for(int m=0;m<32;m++) acc[m] += fs[m][e]*wv;
    }
    #pragma unroll
    for(int m=0;m<32;m++){
      int a = a0+m;
      if(a<NANCH) g_featW[(size_t)a*WO+o] = acc[m];
    }
  }
}

// ---------------- main: keypoints + softmax weights + deformable gather ----------------
__global__ __launch_bounds__(256) void dfa_main_kernel(
    const float* __restrict__ iff, const float* __restrict__ anc,
    const float* __restrict__ pm, const float* __restrict__ wh,
    const float* __restrict__ lfcw, const float* __restrict__ lfcb,
    float* __restrict__ out){
  int n = blockIdx.x;                 // global anchor 0..1799
  int b = n / NA;
  int tid = threadIdx.x;
  int wid = tid>>5, ln = tid&31;

  __shared__ float sIF[E_DIM];
  __shared__ float sA[11];
  __shared__ float sLS[18];
  __shared__ float sKP[NPTS][3];
  __shared__ float sGU[NCAM*NPTS], sGV[NCAM*NPTS];
  __shared__ float sWgt[NCAM*WO];     // 2496: logits -> softmaxed weights, [c][l][p][g]
  __shared__ float sFused[E_DIM];

  // phase 1: loads + init
  sIF[tid] = iff[(size_t)n*E_DIM+tid];
  sFused[tid] = 0.f;
  if(tid<11) sA[tid] = anc[(size_t)n*11+tid];
  __syncthreads();

  // phase 2: learned scales + logits
  if(tid<18){
    float v = lfcb[tid];
    for(int e=0;e<E_DIM;e++) v += sIF[e]*lfcw[e*18+tid];
    sLS[tid] = 1.f/(1.f+__expf(-v)) - 0.5f;
  }
  #pragma unroll
  for(int idx=tid; idx<NCAM*WO; idx+=256){
    int c = idx/WO, o = idx - c*WO;
    sWgt[idx] = g_featW[(size_t)n*WO+o] + g_ceWb[(b*NCAM+c)*WO+o];
  }
  __syncthreads();

  // phase 3: keypoints (warp0 lanes 0..12) + softmax per group (warp g)
  if(tid<NPTS){
    float sx = expf(sA[3]), sy2 = expf(sA[4]), sz = expf(sA[5]);
    float kx,ky,kz;
    if(tid<7){ kx=c_fix[tid][0]*sx; ky=c_fix[tid][1]*sy2; kz=c_fix[tid][2]*sz; }
    else { int i=tid-7; kx=sLS[i*3+0]*sx; ky=sLS[i*3+1]*sy2; kz=sLS[i*3+2]*sz; }
    float sn = sA[6], cs = sA[7];
    sKP[tid][0] = cs*kx - sn*ky + sA[0];
    sKP[tid][1] = sn*kx + cs*ky + sA[1];
    sKP[tid][2] = kz + sA[2];
  }
  {
    int g = wid;
    float mx = -1e30f;
    for(int j=ln;j<SOFTN;j+=32){
      int c=j/52, k=j-c*52;
      mx = fmaxf(mx, sWgt[c*WO + k*8 + g]);
    }
    #pragma unroll
    for(int o=16;o;o>>=1) mx = fmaxf(mx, __shfl_xor_sync(0xffffffffu, mx, o));
    float sum = 0.f;
    for(int j=ln;j<SOFTN;j+=32){
      int c=j/52, k=j-c*52;
      sum += __expf(sWgt[c*WO + k*8 + g] - mx);
    }
    #pragma unroll
    for(int o=16;o;o>>=1) sum += __shfl_xor_sync(0xffffffffu, sum, o);
    float inv = 1.f/sum;
    for(int j=ln;j<SOFTN;j+=32){
      int c=j/52, k=j-c*52;
      int idx = c*WO + k*8 + g;
      sWgt[idx] = __expf(sWgt[idx] - mx) * inv;
    }
  }
  __syncthreads();

  // phase 4: projection (78 threads: c*13+p)
  if(tid < NCAM*NPTS){
    int c = tid/NPTS, p = tid - c*NPTS;
    const float* P = pm + (size_t)(b*NCAM+c)*16;
    float X = sKP[p][0], Y = sKP[p][1], Z = sKP[p][2];
    float r0 = P[0]*X + P[1]*Y + P[2]*Z  + P[3];
    float r1 = P[4]*X + P[5]*Y + P[6]*Z  + P[7];
    float r2 = P[8]*X + P[9]*Y + P[10]*Z + P[11];
    float z = fmaxf(r2, 1e-5f);
    float iwx = wh[(b*NCAM+c)*2+0], iwy = wh[(b*NCAM+c)*2+1];
    sGU[tid] = (r0/z)/iwx*2.f - 1.f;
    sGV[tid] = (r1/z)/iwy*2.f - 1.f;
  }
  __syncthreads();

  // phase 5: sampling. warp w handles samples s = w, w+8, ... (312 total)
  float4 acc0 = make_float4(0,0,0,0);
  float4 acc1 = make_float4(0,0,0,0);
  int g0 = ln>>3;        // group for channels [4*ln .. 4*ln+3]
  int g1 = 4 + (ln>>3);  // group for channels [128+4*ln ..]

  for(int s = wid; s < NSAMP; s += 8){
    int c = s/52, r = s - c*52, l = r/13, p = r - l*13;
    const float* fml; int Wl, Hl;
    if(l==0){ fml=g_fmt0; Wl=176; Hl=64; }
    else if(l==1){ fml=g_fmt1; Wl=88; Hl=32; }
    else if(l==2){ fml=g_fmt2; Wl=44; Hl=16; }
    else { fml=g_fmt3; Wl=22; Hl=8; }
    float fW = (float)Wl, fH = (float)Hl;
    float gu = sGU[c*NPTS+p], gv = sGV[c*NPTS+p];
    float gx = (gu+1.f)*(fW*0.5f) - 0.5f;
    float gy = (gv+1.f)*(fH*0.5f) - 0.5f;
    if(!(gx > -1.f && gx < fW && gy > -1.f && gy < fH)) continue;
    float x0f = floorf(gx), y0f = floorf(gy);
    float wx1 = gx - x0f, wy1 = gy - y0f;
    float wx0 = 1.f - wx1, wy0 = 1.f - wy1;
    int x0 = (int)x0f, y0 = (int)y0f;
    bool vx0 = (x0 >= 0), vx1 = (x0+1 < Wl);
    bool vy0 = (y0 >= 0), vy1 = (y0+1 < Hl);
    const float* imgb = fml + (size_t)(b*NCAM+c)*Hl*Wl*E_DIM;
    float4 s0 = make_float4(0,0,0,0);
    float4 s1 = make_float4(0,0,0,0);
    #define TAP(px, py, wt) { \
      const float4* p4 = (const float4*)(imgb + ((size_t)(py)*Wl + (px))*E_DIM); \
      float4 va = p4[ln]; float4 vb = p4[ln+32]; \
      s0.x += (wt)*va.x; s0.y += (wt)*va.y; s0.z += (wt)*va.z; s0.w += (wt)*va.w; \
      s1.x += (wt)*vb.x; s1.y += (wt)*vb.y; s1.z += (wt)*vb.z; s1.w += (wt)*vb.w; }
    if(vy0){
      if(vx0) TAP(x0,   y0, wx0*wy0);
      if(vx1) TAP(x0+1, y0, wx1*wy0);
    }
    if(vy1){
      if(vx0) TAP(x0,   y0+1, wx0*wy1);
      if(vx1) TAP(x0+1, y0+1, wx1*wy1);
    }
    #undef TAP
    float wtA = sWgt[s*8 + g0];
    float wtB = sWgt[s*8 + g1];
    acc0.x += wtA*s0.x; acc0.y += wtA*s0.y; acc0.z += wtA*s0.z; acc0.w += wtA*s0.w;
    acc1.x += wtB*s1.x; acc1.y += wtB*s1.y; acc1.z += wtB*s1.z; acc1.w += wtB*s1.w;
  }
  // reduce into shared
  atomicAdd(&sFused[4*ln+0], acc0.x);
  atomicAdd(&sFused[4*ln+1], acc0.y);
  atomicAdd(&sFused[4*ln+2], acc0.z);
  atomicAdd(&sFused[4*ln+3], acc0.w);
  atomicAdd(&sFused[128+4*ln+0], acc1.x);
  atomicAdd(&sFused[128+4*ln+1], acc1.y);
  atomicAdd(&sFused[128+4*ln+2], acc1.z);
  atomicAdd(&sFused[128+4*ln+3], acc1.w);
  __syncthreads();

  g_fused[(size_t)n*E_DIM + tid] = sFused[tid];
  out[(size_t)n*512 + 256 + tid] = sIF[tid];   // concat tail
}

// ---------------- final projection: out[:, :256] = fused @ op_w + op_b ----------------
__global__ __launch_bounds__(256) void outproj_kernel(const float* __restrict__ opw,
    const float* __restrict__ opb, float* __restrict__ out){
  __shared__ float fs[32][E_DIM];
  int a0 = blockIdx.x*32;
  int tid = threadIdx.x;
  #pragma unroll 4
  for(int m=0;m<32;m++){
    int a = a0+m;
    fs[m][tid] = (a<NANCH) ? g_fused[(size_t)a*E_DIM+tid] : 0.f;
  }
  __syncthreads();
  float acc[32];
  float bias = opb[tid];
  #pragma unroll
  for(int m=0;m<32;m++) acc[m]=bias;
  for(int e=0;e<E_DIM;e++){
    float wv = opw[e*E_DIM+tid];
    #pragma unroll
    for(int m=0;m<32;m++) acc[m] += fs[m][e]*wv;
  }
  #pragma unroll
  for(int m=0;m<32;m++){
    int a = a0+m;
    if(a<NANCH) out[(size_t)a*512 + tid] = acc[m];
  }
}

// ---------------- host launcher ----------------
extern "C" void kernel_launch(void* const* d_in, const int* in_sizes, int n_in,
                              void* d_out, int out_size) {
  // Input order detection: setup_inputs order has projection_mat (192 elems) at idx 3;
  // reference-signature order has fm0 (34603008) at idx 3.
  int iIF=0, iAE=2, iPM, iWH, iFM0, iFM1, iFM2, iFM3;
  int iANC=1;
  if(in_sizes[3]==192){ iPM=3; iWH=4; iFM0=5; iFM1=6; iFM2=7; iFM3=8; }
  else                { iFM0=3; iFM1=4; iFM2=5; iFM3=6; iPM=7; iWH=8; }
  int iLFW=9, iLFB=10, iC1W=11, iC1B=12, iL1G=13, iL1B=14,
      iC2W=15, iC2B=16, iL2G=17, iL2B=18, iWFW=19, iWFB=20, iOPW=21, iOPB=22;

  const float* iff  = (const float*)d_in[iIF];
  const float* anc  = (const float*)d_in[iANC];
  const float* ae   = (const float*)d_in[iAE];
  const float* pm   = (const float*)d_in[iPM];
  const float* wh   = (const float*)d_in[iWH];
  const float* fm0  = (const float*)d_in[iFM0];
  const float* fm1  = (const float*)d_in[iFM1];
  const float* fm2  = (const float*)d_in[iFM2];
  const float* fm3  = (const float*)d_in[iFM3];
  const float* lfcw = (const float*)d_in[iLFW];
  const float* lfcb = (const float*)d_in[iLFB];
  const float* c1w  = (const float*)d_in[iC1W];
  const float* c1b  = (const float*)d_in[iC1B];
  const float* l1g  = (const float*)d_in[iL1G];
  const float* l1b  = (const float*)d_in[iL1B];
  const float* c2w  = (const float*)d_in[iC2W];
  const float* c2b  = (const float*)d_in[iC2B];
  const float* l2g  = (const float*)d_in[iL2G];
  const float* l2b  = (const float*)d_in[iL2B];
  const float* wfw  = (const float*)d_in[iWFW];
  const float* wfb  = (const float*)d_in[iWFB];
  const float* opw  = (const float*)d_in[iOPW];
  const float* opb  = (const float*)d_in[iOPB];
  float* out = (float*)d_out;

  dim3 tb(32,8,1);
  transpose_kernel<<<dim3(352,8,12), tb>>>(fm0, 0);
  transpose_kernel<<<dim3( 88,8,12), tb>>>(fm1, 1);
  transpose_kernel<<<dim3( 22,8,12), tb>>>(fm2, 2);
  transpose_kernel<<<dim3(  6,8,12), tb>>>(fm3, 3);

  cam_embed_kernel<<<12, 256>>>(pm, c1w, c1b, l1g, l1b, c2w, c2b, l2g, l2b, wfw, wfb);
  featw_kernel<<<(NANCH+31)/32, 256>>>(iff, ae, wfw);
  dfa_main_kernel<<<NANCH, 256>>>(iff, anc, pm, wh, lfcw, lfcb, out);
  outproj_kernel<<<(NANCH+31)/32, 256>>>(opw, opb, out);
}

// round 2
// speedup vs baseline: 1.0847x; 1.0847x over previous
#include <cuda_runtime.h>
#include <math.h>
#include <stdint.h>

// Problem constants
#define E_DIM   256
#define NA      900
#define BS      2
#define NCAM    6
#define NLVL    4
#define NPTS    13
#define NG      8
#define NANCH   (BS*NA)          // 1800
#define WO      416              // G*NL*NPTS = 8*4*13
#define NSAMP   (NCAM*NLVL*NPTS) // 312
#define SOFTN   312              // softmax length per group

// Feature-map level shapes
// level: H, W
// 0: 64,176  1: 32,88  2: 16,44  3: 8,22

// -------- device scratch (no runtime allocation allowed) --------
__device__ float g_fmt0[34603008];   // [12][64*176][256]
__device__ float g_fmt1[8650752];    // [12][32*88][256]
__device__ float g_fmt2[2162688];    // [12][16*44][256]
__device__ float g_fmt3[540672];     // [12][8*22][256]
__device__ float g_featW[NANCH*WO];  // (feat+anchor_embed) @ wfc_w   (no bias)
__device__ float g_ceWb[12*WO];      // ce @ wfc_w + wfc_b
__device__ float g_fused[NANCH*E_DIM];

__constant__ float c_fix[7][3] = {
  {0.f,0.f,0.f},{0.45f,0.f,0.f},{-0.45f,0.f,0.f},{0.f,0.45f,0.f},
  {0.f,-0.45f,0.f},{0.f,0.f,0.45f},{0.f,0.f,-0.45f}};

// ---------------- transpose [b,c,E,H,W] -> [b,c,H,W,E] ----------------
__global__ void transpose_kernel(const float* __restrict__ src, int level){
  float* dst; int HW;
  if(level==0){dst=g_fmt0; HW=11264;} else if(level==1){dst=g_fmt1; HW=2816;}
  else if(level==2){dst=g_fmt2; HW=704;} else {dst=g_fmt3; HW=176;}
  __shared__ float tile[32][33];
  int img = blockIdx.z;
  const float* s = src + (size_t)img * E_DIM * HW;
  float* d       = dst + (size_t)img * HW * E_DIM;
  int hw0 = blockIdx.x*32, e0 = blockIdx.y*32;
  int tx = threadIdx.x, ty = threadIdx.y;
  #pragma unroll
  for(int i=ty;i<32;i+=8){
    int hw = hw0+tx;
    tile[i][tx] = (hw<HW) ? s[(size_t)(e0+i)*HW + hw] : 0.f;
  }
  __syncthreads();
  #pragma unroll
  for(int i=ty;i<32;i+=8){
    int hw = hw0+i;
    if(hw<HW) d[(size_t)hw*E_DIM + (e0+tx)] = tile[tx][i];
  }
}

// ---------------- camera embed: 12 rows MLP + LN, then @wfc_w ----------------
__device__ __forceinline__ float blockSum256(float v, float* red){
  int tid = threadIdx.x;
  red[tid] = v; __syncthreads();
  #pragma unroll
  for(int s=128;s>0;s>>=1){
    if(tid<s) red[tid]+=red[tid+s];
    __syncthreads();
  }
  float r = red[0]; __syncthreads();
  return r;
}

__global__ void cam_embed_kernel(const float* __restrict__ pm,
    const float* __restrict__ ce1w, const float* __restrict__ ce1b,
    const float* __restrict__ ln1g, const float* __restrict__ ln1b,
    const float* __restrict__ ce2w, const float* __restrict__ ce2b,
    const float* __restrict__ ln2g, const float* __restrict__ ln2b,
    const float* __restrict__ wfcw, const float* __restrict__ wfcb){
  int img = blockIdx.x;          // b*6+c, 12 blocks
  int tid = threadIdx.x;         // 256
  __shared__ float cam[12];
  __shared__ float h[E_DIM];
  __shared__ float red[E_DIM];
  if(tid<12) cam[tid] = pm[img*16 + tid];   // first 3 rows of 4x4, row-major
  __syncthreads();
  // layer 1
  float v = ce1b[tid];
  #pragma unroll
  for(int i=0;i<12;i++) v += cam[i]*ce1w[i*E_DIM+tid];
  v = fmaxf(v,0.f);
  float m = blockSum256(v, red) * (1.f/E_DIM);
  float dvar = v - m;
  float var = blockSum256(dvar*dvar, red) * (1.f/E_DIM);
  v = dvar * rsqrtf(var + 1e-5f) * ln1g[tid] + ln1b[tid];
  h[tid] = v; __syncthreads();
  // layer 2
  float v2 = ce2b[tid];
  for(int i=0;i<E_DIM;i++) v2 += h[i]*ce2w[i*E_DIM+tid];
  v2 = fmaxf(v2,0.f);
  __syncthreads();           // h still in use above? loop done; safe before overwrite
  float m2 = blockSum256(v2, red) * (1.f/E_DIM);
  float d2 = v2 - m2;
  float var2 = blockSum256(d2*d2, red) * (1.f/E_DIM);
  v2 = d2 * rsqrtf(var2 + 1e-5f) * ln2g[tid] + ln2b[tid];
  h[tid] = v2; __syncthreads();
  // ceWb = ce @ wfc_w + wfc_b
  for(int o=tid;o<WO;o+=256){
    float a = wfcb[o];
    for(int e=0;e<E_DIM;e++) a += h[e]*wfcw[e*WO+o];
    g_ceWb[img*WO+o] = a;
  }
}

// ---------------- featW = (instance_feature + anchor_embed) @ wfc_w ----------------
__global__ __launch_bounds__(256) void featw_kernel(const float* __restrict__ iff,
    const float* __restrict__ ae, const float* __restrict__ wfcw){
  __shared__ float fs[32][E_DIM];
  int a0 = blockIdx.x*32;
  int tid = threadIdx.x;
  #pragma unroll 4
  for(int m=0;m<32;m++){
    int a = a0+m;
    fs[m][tid] = (a<NANCH) ? (iff[(size_t)a*E_DIM+tid] + ae[(size_t)a*E_DIM+tid]) : 0.f;
  }
  __syncthreads();
  for(int o=tid;o<WO;o+=256){
    float acc[32];
    #pragma unroll
    for(int m=0;m<32;m++) acc[m]=0.f;
    for(int e=0;e<E_DIM;e++){
      float wv = wfcw[e*WO+o];
      #pragma unroll
      for(int m=0;m<32;m++) acc[m] += fs[m][e]*wv;
    }
    #pragma unroll
    for(int m=0;m<32;m++){
      int a = a0+m;
      if(a<NANCH) g_featW[(size_t)a*WO+o] = acc[m];
    }
  }
}

// ---------------- main: keypoints + softmax weights + deformable gather ----------------
__global__ __launch_bounds__(256) void dfa_main_kernel(
    const float* __restrict__ iff, const float* __restrict__ anc,
    const float* __restrict__ pm, const float* __restrict__ wh,
    const float* __restrict__ lfcw, const float* __restrict__ lfcb,
    float* __restrict__ out){
  int n = blockIdx.x;                 // global anchor 0..1799
  int b = n / NA;
  int tid = threadIdx.x;
  int wid = tid>>5, ln = tid&31;

  __shared__ float sIF[E_DIM];
  __shared__ float sA[11];
  __shared__ float sLS[18];
  __shared__ float sKP[NPTS][3];
  __shared__ float sGU[NCAM*NPTS], sGV[NCAM*NPTS];
  __shared__ float sWgt[NCAM*WO];     // 2496: logits -> softmaxed weights, [c][l][p][g]
  __shared__ float sFused[E_DIM];

  // phase 1: loads + init
  sIF[tid] = iff[(size_t)n*E_DIM+tid];
  sFused[tid] = 0.f;
  if(tid<11) sA[tid] = anc[(size_t)n*11+tid];
  __syncthreads();

  // phase 2: learned scales + logits
  if(tid<18){
    float v = lfcb[tid];
    for(int e=0;e<E_DIM;e++) v += sIF[e]*lfcw[e*18+tid];
    sLS[tid] = 1.f/(1.f+__expf(-v)) - 0.5f;
  }
  #pragma unroll
  for(int idx=tid; idx<NCAM*WO; idx+=256){
    int c = idx/WO, o = idx - c*WO;
    sWgt[idx] = g_featW[(size_t)n*WO+o] + g_ceWb[(b*NCAM+c)*WO+o];
  }
  __syncthreads();

  // phase 3: keypoints (warp0 lanes 0..12) + softmax per group (warp g)
  if(tid<NPTS){
    float sx = expf(sA[3]), sy2 = expf(sA[4]), sz = expf(sA[5]);
    float kx,ky,kz;
    if(tid<7){ kx=c_fix[tid][0]*sx; ky=c_fix[tid][1]*sy2; kz=c_fix[tid][2]*sz; }
    else { int i=tid-7; kx=sLS[i*3+0]*sx; ky=sLS[i*3+1]*sy2; kz=sLS[i*3+2]*sz; }
    float sn = sA[6], cs = sA[7];
    sKP[tid][0] = cs*kx - sn*ky + sA[0];
    sKP[tid][1] = sn*kx + cs*ky + sA[1];
    sKP[tid][2] = kz + sA[2];
  }
  {
    int g = wid;
    float mx = -1e30f;
    for(int j=ln;j<SOFTN;j+=32){
      int c=j/52, k=j-c*52;
      mx = fmaxf(mx, sWgt[c*WO + k*8 + g]);
    }
    #pragma unroll
    for(int o=16;o;o>>=1) mx = fmaxf(mx, __shfl_xor_sync(0xffffffffu, mx, o));
    float sum = 0.f;
    for(int j=ln;j<SOFTN;j+=32){
      int c=j/52, k=j-c*52;
      sum += __expf(sWgt[c*WO + k*8 + g] - mx);
    }
    #pragma unroll
    for(int o=16;o;o>>=1) sum += __shfl_xor_sync(0xffffffffu, sum, o);
    float inv = 1.f/sum;
    for(int j=ln;j<SOFTN;j+=32){
      int c=j/52, k=j-c*52;
      int idx = c*WO + k*8 + g;
      sWgt[idx] = __expf(sWgt[idx] - mx) * inv;
    }
  }
  __syncthreads();

  // phase 4: projection (78 threads: c*13+p)
  if(tid < NCAM*NPTS){
    int c = tid/NPTS, p = tid - c*NPTS;
    const float* P = pm + (size_t)(b*NCAM+c)*16;
    float X = sKP[p][0], Y = sKP[p][1], Z = sKP[p][2];
    float r0 = P[0]*X + P[1]*Y + P[2]*Z  + P[3];
    float r1 = P[4]*X + P[5]*Y + P[6]*Z  + P[7];
    float r2 = P[8]*X + P[9]*Y + P[10]*Z + P[11];
    float z = fmaxf(r2, 1e-5f);
    float iwx = wh[(b*NCAM+c)*2+0], iwy = wh[(b*NCAM+c)*2+1];
    sGU[tid] = (r0/z)/iwx*2.f - 1.f;
    sGV[tid] = (r1/z)/iwy*2.f - 1.f;
  }
  __syncthreads();

  // phase 5: sampling. warp w handles samples s = w, w+8, ... (312 total)
  float4 acc0 = make_float4(0,0,0,0);
  float4 acc1 = make_float4(0,0,0,0);
  int g0 = ln>>3;        // group for channels [4*ln .. 4*ln+3]
  int g1 = 4 + (ln>>3);  // group for channels [128+4*ln ..]

  for(int s = wid; s < NSAMP; s += 8){
    int c = s/52, r = s - c*52, l = r/13, p = r - l*13;
    const float* fml; int Wl, Hl;
    if(l==0){ fml=g_fmt0; Wl=176; Hl=64; }
    else if(l==1){ fml=g_fmt1; Wl=88; Hl=32; }
    else if(l==2){ fml=g_fmt2; Wl=44; Hl=16; }
    else { fml=g_fmt3; Wl=22; Hl=8; }
    float fW = (float)Wl, fH = (float)Hl;
    float gu = sGU[c*NPTS+p], gv = sGV[c*NPTS+p];
    float gx = (gu+1.f)*(fW*0.5f) - 0.5f;
    float gy = (gv+1.f)*(fH*0.5f) - 0.5f;
    if(!(gx > -1.f && gx < fW && gy > -1.f && gy < fH)) continue;
    float x0f = floorf(gx), y0f = floorf(gy);
    float wx1 = gx - x0f, wy1 = gy - y0f;
    float wx0 = 1.f - wx1, wy0 = 1.f - wy1;
    int x0 = (int)x0f, y0 = (int)y0f;
    bool vx0 = (x0 >= 0), vx1 = (x0+1 < Wl);
    bool vy0 = (y0 >= 0), vy1 = (y0+1 < Hl);
    const float* imgb = fml + (size_t)(b*NCAM+c)*Hl*Wl*E_DIM;
    float4 s0 = make_float4(0,0,0,0);
    float4 s1 = make_float4(0,0,0,0);
    #define TAP(px, py, wt) { \
      const float4* p4 = (const float4*)(imgb + ((size_t)(py)*Wl + (px))*E_DIM); \
      float4 va = p4[ln]; float4 vb = p4[ln+32]; \
      s0.x += (wt)*va.x; s0.y += (wt)*va.y; s0.z += (wt)*va.z; s0.w += (wt)*va.w; \
      s1.x += (wt)*vb.x; s1.y += (wt)*vb.y; s1.z += (wt)*vb.z; s1.w += (wt)*vb.w; }
    if(vy0){
      if(vx0) TAP(x0,   y0, wx0*wy0);
      if(vx1) TAP(x0+1, y0, wx1*wy0);
    }
    if(vy1){
      if(vx0) TAP(x0,   y0+1, wx0*wy1);
      if(vx1) TAP(x0+1, y0+1, wx1*wy1);
    }
    #undef TAP
    float wtA = sWgt[s*8 + g0];
    float wtB = sWgt[s*8 + g1];
    acc0.x += wtA*s0.x; acc0.y += wtA*s0.y; acc0.z += wtA*s0.z; acc0.w += wtA*s0.w;
    acc1.x += wtB*s1.x; acc1.y += wtB*s1.y; acc1.z += wtB*s1.z; acc1.w += wtB*s1.w;
  }
  // reduce into shared
  atomicAdd(&sFused[4*ln+0], acc0.x);
  atomicAdd(&sFused[4*ln+1], acc0.y);
  atomicAdd(&sFused[4*ln+2], acc0.z);
  atomicAdd(&sFused[4*ln+3], acc0.w);
  atomicAdd(&sFused[128+4*ln+0], acc1.x);
  atomicAdd(&sFused[128+4*ln+1], acc1.y);
  atomicAdd(&sFused[128+4*ln+2], acc1.z);
  atomicAdd(&sFused[128+4*ln+3], acc1.w);
  __syncthreads();

  g_fused[(size_t)n*E_DIM + tid] = sFused[tid];
  out[(size_t)n*512 + 256 + tid] = sIF[tid];   // concat tail
}

// ---------------- final projection: out[:, :256] = fused @ op_w + op_b ----------------
__global__ __launch_bounds__(256) void outproj_kernel(const float* __restrict__ opw,
    const float* __restrict__ opb, float* __restrict__ out){
  __shared__ float fs[32][E_DIM];
  int a0 = blockIdx.x*32;
  int tid = threadIdx.x;
  #pragma unroll 4
  for(int m=0;m<32;m++){
    int a = a0+m;
    fs[m][tid] = (a<NANCH) ? g_fused[(size_t)a*E_DIM+tid] : 0.f;
  }
  __syncthreads();
  float acc[32];
  float bias = opb[tid];
  #pragma unroll
  for(int m=0;m<32;m++) acc[m]=bias;
  for(int e=0;e<E_DIM;e++){
    float wv = opw[e*E_DIM+tid];
    #pragma unroll
    for(int m=0;m<32;m++) acc[m] += fs[m][e]*wv;
  }
  #pragma unroll
  for(int m=0;m<32;m++){
    int a = a0+m;
    if(a<NANCH) out[(size_t)a*512 + tid] = acc[m];
  }
}

// ---------------- host launcher ----------------
extern "C" void kernel_launch(void* const* d_in, const int* in_sizes, int n_in,
                              void* d_out, int out_size) {
  // Input order detection: setup_inputs order has projection_mat (192 elems) at idx 3;
  // reference-signature order has fm0 (34603008) at idx 3.
  int iIF=0, iAE=2, iPM, iWH, iFM0, iFM1, iFM2, iFM3;
  int iANC=1;
  if(in_sizes[3]==192){ iPM=3; iWH=4; iFM0=5; iFM1=6; iFM2=7; iFM3=8; }
  else                { iFM0=3; iFM1=4; iFM2=5; iFM3=6; iPM=7; iWH=8; }
  int iLFW=9, iLFB=10, iC1W=11, iC1B=12, iL1G=13, iL1B=14,
      iC2W=15, iC2B=16, iL2G=17, iL2B=18, iWFW=19, iWFB=20, iOPW=21, iOPB=22;

  const float* iff  = (const float*)d_in[iIF];
  const float* anc  = (const float*)d_in[iANC];
  const float* ae   = (const float*)d_in[iAE];
  const float* pm   = (const float*)d_in[iPM];
  const float* wh   = (const float*)d_in[iWH];
  const float* fm0  = (const float*)d_in[iFM0];
  const float* fm1  = (const float*)d_in[iFM1];
  const float* fm2  = (const float*)d_in[iFM2];
  const float* fm3  = (const float*)d_in[iFM3];
  const float* lfcw = (const float*)d_in[iLFW];
  const float* lfcb = (const float*)d_in[iLFB];
  const float* c1w  = (const float*)d_in[iC1W];
  const float* c1b  = (const float*)d_in[iC1B];
  const float* l1g  = (const float*)d_in[iL1G];
  const float* l1b  = (const float*)d_in[iL1B];
  const float* c2w  = (const float*)d_in[iC2W];
  const float* c2b  = (const float*)d_in[iC2B];
  const float* l2g  = (const float*)d_in[iL2G];
  const float* l2b  = (const float*)d_in[iL2B];
  const float* wfw  = (const float*)d_in[iWFW];
  const float* wfb  = (const float*)d_in[iWFB];
  const float* opw  = (const float*)d_in[iOPW];
  const float* opb  = (const float*)d_in[iOPB];
  float* out = (float*)d_out;

  dim3 tb(32,8,1);
  transpose_kernel<<<dim3(352,8,12), tb>>>(fm0, 0);
  transpose_kernel<<<dim3( 88,8,12), tb>>>(fm1, 1);
  transpose_kernel<<<dim3( 22,8,12), tb>>>(fm2, 2);
  transpose_kernel<<<dim3(  6,8,12), tb>>>(fm3, 3);

  cam_embed_kernel<<<12, 256>>>(pm, c1w, c1b, l1g, l1b, c2w, c2b, l2g, l2b, wfw, wfb);
  featw_kernel<<<(NANCH+31)/32, 256>>>(iff, ae, wfw);
  dfa_main_kernel<<<NANCH, 256>>>(iff, anc, pm, wh, lfcw, lfcb, out);
  outproj_kernel<<<(NANCH+31)/32, 256>>>(opw, opb, out);
}